// round 3
// baseline (speedup 1.0000x reference)
#include <cuda_runtime.h>
#include <cstdint>

#define Nn 2048
#define Dd 64
#define Vv 2048
#define TB 128                      // pair tile dim
#define NT (Nn / TB)                // 16 tiles per dim
#define NTILES (NT * (NT + 1) / 2)  // 136 triangle tiles
#define GRID 148                    // one persistent block per SM
#define PADK 33                     // float2 row stride (pad) -> conflict-free
#define NCHUNK 512                  // table work-steal chunks
#define CH_F4 ((Vv * Vv / 4) / NCHUNK)  // float4 per chunk (2048)

// Scratch (no allocations allowed -> __device__ globals)
__device__ float g_table[(size_t)Vv * Vv];   // fused metric table, 16MB
__device__ unsigned g_maxbits;
__device__ float g_sum, g_cnt;
__device__ unsigned g_bar0, g_bar1, g_work;

__global__ void k_init() {
    g_maxbits = 0u; g_sum = 0.0f; g_cnt = 0.0f;
    g_bar0 = 0u; g_bar1 = 0u; g_work = 0u;
}

__global__ void k_final(float* out) { out[0] = g_sum / g_cnt; }

// ---------------------------------------------------------------------------
__device__ __forceinline__ unsigned long long f2add(unsigned long long a,
                                                    unsigned long long b) {
    unsigned long long r;
    asm("add.rn.f32x2 %0, %1, %2;" : "=l"(r) : "l"(a), "l"(b));
    return r;
}

// all-resident grid barrier (grid == 148 == #SMs at occ 1 -> no deadlock)
__device__ __forceinline__ void grid_bar(unsigned* bar) {
    __syncthreads();
    if (threadIdx.x == 0) {
        __threadfence();                 // order prior STGs before arrival
        atomicAdd(bar, 1u);
        while (*(volatile unsigned*)bar < GRID) {}
    }
    __syncthreads();
}

extern __shared__ unsigned long long smem_raw[];

// 1024 threads: thread (tx = tid&31, ty = tid>>5) owns 4x4 pairs:
// rows ty + 32r (r<4), cols tx + 32c (c<4). a-loads are warp-broadcast
// (ty uniform per warp); b-loads stride PADK u64 are conflict-free per
// 16-thread LDS.64 phase.
__global__ __launch_bounds__(1024, 1) void k_fused(
        const int* __restrict__ ids, const float2* __restrict__ emb,
        const float4* __restrict__ tree, const float4* __restrict__ mapd) {
    int tid = threadIdx.x, bid = blockIdx.x;
    int lane = tid & 31, w = tid >> 5;
    __shared__ float sred[32];
    __shared__ float rsum[32], rcnt[32];

    // ---- phase 1: global max over map_dist (all blocks) ----
    {
        float v = 0.0f;
        for (int i = bid * 1024 + tid; i < (Vv * Vv / 4); i += GRID * 1024) {
            float4 x = mapd[i];
            v = fmaxf(fmaxf(v, fmaxf(x.x, x.y)), fmaxf(x.z, x.w));
        }
#pragma unroll
        for (int o = 16; o; o >>= 1) v = fmaxf(v, __shfl_xor_sync(0xffffffffu, v, o));
        if (lane == 0) sred[w] = v;
        __syncthreads();
        if (w == 0) {
            v = sred[lane];
#pragma unroll
            for (int o = 16; o; o >>= 1) v = fmaxf(v, __shfl_xor_sync(0xffffffffu, v, o));
            if (lane == 0) atomicMax(&g_maxbits, __float_as_uint(v));
        }
    }
    grid_bar(&g_bar0);
    float sc = 0.5f / __uint_as_float(g_maxbits);

    // ---- phase 2: compute blocks run the mainloop; helper blocks (and
    //      finished compute blocks) build the fused table via work-steal ----
    unsigned long long* sA = smem_raw;               // [128][PADK] f32x2
    unsigned long long* sB = smem_raw + TB * PADK;   // negated j-tile
    int* sIdI = (int*)(smem_raw + 2 * TB * PADK);
    int* sIdJ = sIdI + TB;

    unsigned long long acc[4][4];
    int ibase = 0, jbase = 0;
    bool offdiag = false;
    bool is_compute = (bid < NTILES);
    int tx = tid & 31, ty = tid >> 5;

    if (is_compute) {
        int t = bid, bi = 0;
        while (t >= NT - bi) { t -= NT - bi; bi++; }
        int bj = bi + t;
        ibase = bi * TB; jbase = bj * TB; offdiag = (bi != bj);

        // load embedding tiles (coalesced; B negated so diff = packed add)
        for (int x = tid; x < TB * 32; x += 1024) {
            int row = x >> 5, k2 = x & 31;
            float2 a = emb[(ibase + row) * 32 + k2];
            float2 b = emb[(jbase + row) * 32 + k2];
            ((float2*)sA)[row * PADK + k2] = a;
            b.x = -b.x; b.y = -b.y;
            ((float2*)sB)[row * PADK + k2] = b;
        }
        if (tid < TB) {
            sIdI[tid] = ids[ibase + tid];
            sIdJ[tid] = ids[jbase + tid];
        }
        __syncthreads();

#pragma unroll
        for (int r = 0; r < 4; r++)
#pragma unroll
            for (int c = 0; c < 4; c++) acc[r][c] = 0ull;

        const unsigned long long ABSM = 0x7FFFFFFF7FFFFFFFull;
        const unsigned long long* sArow = sA + ty * PADK;
        const unsigned long long* sBrow = sB + tx * PADK;

#pragma unroll 2
        for (int k2 = 0; k2 < 32; k2++) {
            unsigned long long a2[4], b2[4];
#pragma unroll
            for (int r = 0; r < 4; r++) a2[r] = sArow[(32 * r) * PADK + k2];
#pragma unroll
            for (int c = 0; c < 4; c++) b2[c] = sBrow[(32 * c) * PADK + k2];
#pragma unroll
            for (int r = 0; r < 4; r++) {
#pragma unroll
                for (int c = 0; c < 4; c++) {
                    unsigned long long d = f2add(a2[r], b2[c]);  // a - b
                    d &= ABSM;                                   // |.| packed
                    acc[r][c] = f2add(acc[r][c], d);
                }
            }
        }
    }

    // table build (work-steal): helpers start immediately, compute blocks join
    {
        const float4* tr = tree;
        const float4* mp = mapd;
        float4* tb = (float4*)g_table;
        for (;;) {
            unsigned ch;
            if (tid == 0) sred[0] = __uint_as_float(atomicAdd(&g_work, 1u));
            __syncthreads();
            ch = __float_as_uint(sred[0]);
            __syncthreads();
            if (ch >= NCHUNK) break;
            int base = ch * CH_F4;
#pragma unroll 2
            for (int i = tid; i < CH_F4; i += 1024) {
                float4 t4 = tr[base + i], m4 = mp[base + i];
                float4 o;
                o.x = 0.5f * t4.x + sc * m4.x;
                o.y = 0.5f * t4.y + sc * m4.y;
                o.z = 0.5f * t4.z + sc * m4.z;
                o.w = 0.5f * t4.w + sc * m4.w;
                tb[base + i] = o;
            }
        }
    }
    grid_bar(&g_bar1);   // table complete + visible

    // ---- phase 3: epilogue gathers (compute blocks only) ----
    if (is_compute) {
        float loss = 0.0f, cnt = 0.0f;
        const float inv64 = 1.0f / 64.0f;
#pragma unroll
        for (int r = 0; r < 4; r++) {
            int ir = ty + 32 * r;
            int idi = sIdI[ir];
            int gi = ibase + ir;
            const float* trow = g_table + (size_t)idi * Vv;
#pragma unroll
            for (int c = 0; c < 4; c++) {
                int jc = tx + 32 * c;
                int idj = sIdJ[jc];
                int gj = jbase + jc;
                if ((offdiag || gi < gj) && idi != idj) {
                    unsigned long long v = acc[r][c];
                    float lo = __uint_as_float((unsigned)v);
                    float hi = __uint_as_float((unsigned)(v >> 32));
                    float ed = (lo + hi) * inv64;
                    loss += fabsf(ed - __ldg(trow + idj));
                    cnt += 1.0f;
                }
            }
        }
#pragma unroll
        for (int o = 16; o; o >>= 1) {
            loss += __shfl_xor_sync(0xffffffffu, loss, o);
            cnt  += __shfl_xor_sync(0xffffffffu, cnt, o);
        }
        if (lane == 0) { rsum[w] = loss; rcnt[w] = cnt; }
        __syncthreads();
        if (tid == 0) {
            float L = 0.0f, C = 0.0f;
#pragma unroll
            for (int i = 0; i < 32; i++) { L += rsum[i]; C += rcnt[i]; }
            atomicAdd(&g_sum, L);
            atomicAdd(&g_cnt, C);
        }
    }
}

// ---------------------------------------------------------------------------
extern "C" void kernel_launch(void* const* d_in, const int* in_sizes, int n_in,
                              void* d_out, int out_size) {
    const int*   ids  = (const int*)d_in[0];
    const float* emb  = (const float*)d_in[1];
    const float* tree = (const float*)d_in[2];
    const float* mapd = (const float*)d_in[3];
    float* out = (float*)d_out;

    const int SMEM_BYTES = 2 * TB * PADK * 8 + 2 * TB * 4;  // ~68.6 KB
    cudaFuncSetAttribute(k_fused, cudaFuncAttributeMaxDynamicSharedMemorySize,
                         SMEM_BYTES);

    k_init<<<1, 1>>>();
    k_fused<<<GRID, 1024, SMEM_BYTES>>>(ids, (const float2*)emb,
                                        (const float4*)tree, (const float4*)mapd);
    k_final<<<1, 1>>>(out);
}